// round 11
// baseline (speedup 1.0000x reference)
#include <cuda_runtime.h>
#include <cuda_bf16.h>

#define BS_      1024
#define D_       1024
#define NEG_     32
#define V_       (D_ / 4)          // 256 float4 per row
#define THREADS_ 256
#define TEMPERATURE_ 0.05f
#define CLS_W_       0.2f
#define EPS_         1e-8f

__device__ float        g_row_loss[BS_];
__device__ unsigned int g_ctr = 0;

static __device__ __forceinline__ float warp_sum(float v) {
    #pragma unroll
    for (int o = 16; o > 0; o >>= 1)
        v += __shfl_xor_sync(0xffffffffu, v, o);
    return v;
}

static __device__ __forceinline__ float dot4(float4 a, float4 b) {
    return a.x * b.x + a.y * b.y + a.z * b.z + a.w * b.w;
}

__global__ __launch_bounds__(THREADS_)
void cls_fused_kernel(const float4* __restrict__ q,
                      const float4* __restrict__ p,
                      const float4* __restrict__ neg,
                      float* __restrict__ out) {
    const int b    = blockIdx.x;
    const int t    = threadIdx.x;
    const int lane = t & 31;
    const int w    = t >> 5;

    // q row staged in shared memory (4 KB) — frees 32 regs vs register cache.
    __shared__ float4 sq[V_];
    __shared__ float  s_qn[NEG_], s_nn[NEG_];
    __shared__ float  s_qq[8], s_pp[8], s_qp[8];

    sq[t] = q[b * V_ + t];

    // Balanced pos-row work: warp w handles float4 slice [w*32 + lane].
    {
        const int idx = w * 32 + lane;
        float4 qe = q[b * V_ + idx];
        float4 pe = p[b * V_ + idx];
        float qq = warp_sum(dot4(qe, qe));
        float pp = warp_sum(dot4(pe, pe));
        float qp = warp_sum(dot4(qe, pe));
        if (lane == 0) { s_qq[w] = qq; s_pp[w] = pp; s_qp[w] = qp; }
    }
    __syncthreads();

    // Warp w owns negatives 4w..4w+3. nv batch of 8 LDG.128 in flight;
    // qv slices re-read from smem (conflict-free, 16B/lane stride).
    const float4* nb = neg + (size_t)b * NEG_ * V_;
    float accq[4], accn[4];
    #pragma unroll
    for (int k = 0; k < 4; k++) {
        const float4* rn = nb + (4 * w + k) * V_;
        float4 nv[8];
        #pragma unroll
        for (int j = 0; j < 8; j++)
            nv[j] = rn[j * 32 + lane];
        float qn = 0.f, nn = 0.f;
        #pragma unroll
        for (int j = 0; j < 8; j++) {
            float4 qv = sq[j * 32 + lane];
            qn += dot4(qv, nv[j]);
            nn += dot4(nv[j], nv[j]);
        }
        accq[k] = qn;
        accn[k] = nn;
    }
    #pragma unroll
    for (int k = 0; k < 4; k++) {
        float qn = warp_sum(accq[k]);
        float nn = warp_sum(accn[k]);
        if (lane == 0) {
            s_qn[4 * w + k] = qn;
            s_nn[4 * w + k] = nn;
        }
    }
    __syncthreads();

    if (t == 0) {
        float qq = 0.f, pp = 0.f, qp = 0.f;
        #pragma unroll
        for (int i = 0; i < 8; i++) { qq += s_qq[i]; pp += s_pp[i]; qp += s_qp[i]; }

        const float inv_T = 1.0f / TEMPERATURE_;
        float qnorm = fmaxf(sqrtf(qq), EPS_);
        float pnorm = fmaxf(sqrtf(pp), EPS_);
        float sim0  = qp / (qnorm * pnorm) * inv_T;

        float sims[NEG_];
        float m = sim0;
        #pragma unroll
        for (int n = 0; n < NEG_; n++) {
            float nn = fmaxf(sqrtf(s_nn[n]), EPS_);
            float s  = s_qn[n] / (qnorm * nn) * inv_T;
            sims[n] = s;
            m = fmaxf(m, s);
        }
        float se = __expf(sim0 - m);
        #pragma unroll
        for (int n = 0; n < NEG_; n++)
            se += __expf(sims[n] - m);
        g_row_loss[b] = (m + __logf(se)) - sim0;   // -log_softmax[:, 0]
    }

    // ---- last-CTA final reduction (fused; saves the 4.3us second launch) ----
    __shared__ bool s_last;
    __threadfence();
    if (t == 0) {
        unsigned int prev = atomicInc(&g_ctr, BS_ - 1);  // wraps to 0 at BS_-1
        s_last = (prev == BS_ - 1);
    }
    __syncthreads();
    if (!s_last) return;
    __threadfence();  // acquire side: order g_row_loss reads after the atomic

    // Fixed-order deterministic sum: thread t owns rows t, t+256, t+512, t+768.
    float v = 0.f;
    #pragma unroll
    for (int r = 0; r < BS_ / THREADS_; r++)
        v += g_row_loss[t + r * THREADS_];
    v = warp_sum(v);
    __shared__ float s_fin[8];
    if (lane == 0) s_fin[w] = v;
    __syncthreads();
    if (t == 0) {
        float s = 0.f;
        #pragma unroll
        for (int i = 0; i < 8; i++) s += s_fin[i];
        out[0] = s * (CLS_W_ / (float)BS_);
    }
}

extern "C" void kernel_launch(void* const* d_in, const int* in_sizes, int n_in,
                              void* d_out, int out_size) {
    const float4* q   = (const float4*)d_in[0];  // text_embeddings     [1024,1024]
    const float4* p   = (const float4*)d_in[1];  // text_pos_embeddings [1024,1024]
    const float4* neg = (const float4*)d_in[2];  // text_neg_embeddings [32768,1024]
    float* out = (float*)d_out;

    cls_fused_kernel<<<BS_, THREADS_>>>(q, p, neg, out);
}